// round 8
// baseline (speedup 1.0000x reference)
#include <cuda_runtime.h>
#include <cuda_bf16.h>
#include <math_constants.h>
#include <cstdint>

// Problem constants
#define PB 2
#define PS 2048
#define PE 1024
#define PH 16
#define PHD 64
#define PBH (PB * PH)        // 32
#define PM (PB * PS)         // 4096

// ---------------------------------------------------------------------------
// PTX helpers (sm_100-safe: mma.sync + cp.async only, NO tcgen05)
// ---------------------------------------------------------------------------
__device__ __forceinline__ uint32_t f2tf32(float f) {
    uint32_t u; asm("cvt.rna.tf32.f32 %0, %1;" : "=r"(u) : "f"(f)); return u;
}
__device__ __forceinline__ void mma_tf32(float c[4], const uint32_t a[4], const uint32_t b[2]) {
    asm("mma.sync.aligned.m16n8k8.row.col.f32.tf32.tf32.f32 "
        "{%0,%1,%2,%3}, {%4,%5,%6,%7}, {%8,%9}, {%0,%1,%2,%3};"
        : "+f"(c[0]), "+f"(c[1]), "+f"(c[2]), "+f"(c[3])
        : "r"(a[0]), "r"(a[1]), "r"(a[2]), "r"(a[3]), "r"(b[0]), "r"(b[1]));
}
__device__ __forceinline__ uint32_t smem_u32(const void* p) {
    uint32_t a;
    asm("{ .reg .u64 t; cvta.to.shared.u64 t, %1; cvt.u32.u64 %0, t; }" : "=r"(a) : "l"(p));
    return a;
}
__device__ __forceinline__ void cp16(uint32_t s, const void* g) {
    asm volatile("cp.async.cg.shared.global [%0], [%1], 16;" :: "r"(s), "l"(g) : "memory");
}
#define CP_COMMIT() asm volatile("cp.async.commit_group;" ::: "memory")
#define CP_WAIT0()  asm volatile("cp.async.wait_group 0;" ::: "memory")

// ---------------------------------------------------------------------------
// Scratch (no cudaMalloc allowed)
// ---------------------------------------------------------------------------
__device__ float g_qp[PM * PE];
__device__ float g_kp[PM * PE];
__device__ float g_vp[PM * PE];
__device__ float g_ao[PM * PE];

// ---------------------------------------------------------------------------
// TF32 GEMM v2: C[M,N] = A[M,K] @ B[N,K]^T  (torch Linear)
// CTA tile 128x256, 8 warps (2 wm x 4 wn), warp tile 64x64 -> 16 FLOP/smem-byte
// (2x the old 64x32 warp tile). K-tile 32. cp.async raw-f32 staging, pitch 36
// (fragment LDS bank = 4*gr + cc, conflict-free). tf32 cvt at fragment load.
// 128 fp32 accumulators per thread.
// ---------------------------------------------------------------------------
#define GP   36
#define SMA  (128 * GP)             // floats per A buffer
#define SMB  (256 * GP)             // floats per B buffer
#define GT_SMEM ((SMA + SMB) * 2 * 4)   // 110592 bytes

__global__ __launch_bounds__(256, 1)
void gemm_tc(const float* __restrict__ A0, const float* __restrict__ B0, float* __restrict__ C0,
             const float* __restrict__ A1, const float* __restrict__ B1, float* __restrict__ C1,
             const float* __restrict__ A2, const float* __restrict__ B2, float* __restrict__ C2,
             int M, int N, int K)
{
    extern __shared__ float smf[];
    const uint32_t sb = smem_u32(smf);

    const float* A = A0; const float* B = B0; float* C = C0;
    if (blockIdx.z == 1) { A = A1; B = B1; C = C1; }
    else if (blockIdx.z == 2) { A = A2; B = B2; C = C2; }

    const int tid  = threadIdx.x;
    const int lane = tid & 31;
    const int warp = tid >> 5;
    const int wm   = warp >> 2;          // 0..1  (64 rows each)
    const int wn   = warp & 3;           // 0..3  (64 cols each)
    const int gr   = lane >> 2;          // 0..7
    const int cc   = lane & 3;           // 0..3

    const int bm = blockIdx.y * 128;
    const int bn = blockIdx.x * 256;

    // staging maps
    const int raA = tid >> 1;            // A row 0..127
    const int kcA = (tid & 1) * 16;      // 16 floats (4 chunks)
    const float* Agp = A + (size_t)(bm + raA) * K + kcA;
    const uint32_t AsO = (raA * GP + kcA) * 4;
    const float* Bgp = B + (size_t)(bn + tid) * K;   // B row = tid (0..255)
    const uint32_t BsO = (tid * GP) * 4;

    float acc[4][8][4];
#pragma unroll
    for (int mt = 0; mt < 4; mt++)
#pragma unroll
        for (int nt = 0; nt < 8; nt++)
#pragma unroll
            for (int r = 0; r < 4; r++) acc[mt][nt][r] = 0.f;

    const uint32_t bufBytes = (SMA + SMB) * 4;

    // prologue: stage tile 0 into buffer 0
    {
        const uint32_t aB = sb, bB = sb + SMA * 4;
#pragma unroll
        for (int i = 0; i < 4; i++) cp16(aB + AsO + i * 16, Agp + i * 4);
#pragma unroll
        for (int i = 0; i < 8; i++) cp16(bB + BsO + i * 16, Bgp + i * 4);
        CP_COMMIT();
    }

    const int NT = K / 32;
    uint32_t buf = 0;
    for (int t = 0; t < NT; t++) {
        CP_WAIT0();
        __syncthreads();

        if (t + 1 < NT) {
            const uint32_t nb = buf ^ 1;
            const uint32_t aB = sb + nb * bufBytes, bB = aB + SMA * 4;
            const int ko = (t + 1) * 32;
#pragma unroll
            for (int i = 0; i < 4; i++) cp16(aB + AsO + i * 16, Agp + ko + i * 4);
#pragma unroll
            for (int i = 0; i < 8; i++) cp16(bB + BsO + i * 16, Bgp + ko + i * 4);
            CP_COMMIT();
        }

        const float* As = smf + buf * (SMA + SMB);
        const float* Bs = As + SMA;

#pragma unroll
        for (int ks = 0; ks < 4; ks++) {
            const int k8 = ks * 8;
            uint32_t afr[4][4], bfr[8][2];
#pragma unroll
            for (int mt = 0; mt < 4; mt++) {
                const int r0 = wm * 64 + mt * 16 + gr;
                afr[mt][0] = f2tf32(As[r0 * GP + k8 + cc]);
                afr[mt][1] = f2tf32(As[(r0 + 8) * GP + k8 + cc]);
                afr[mt][2] = f2tf32(As[r0 * GP + k8 + cc + 4]);
                afr[mt][3] = f2tf32(As[(r0 + 8) * GP + k8 + cc + 4]);
            }
#pragma unroll
            for (int nt = 0; nt < 8; nt++) {
                const int nr = wn * 64 + nt * 8 + gr;
                bfr[nt][0] = f2tf32(Bs[nr * GP + k8 + cc]);
                bfr[nt][1] = f2tf32(Bs[nr * GP + k8 + cc + 4]);
            }
#pragma unroll
            for (int mt = 0; mt < 4; mt++)
#pragma unroll
                for (int nt = 0; nt < 8; nt++)
                    mma_tf32(acc[mt][nt], afr[mt], bfr[nt]);
        }
        buf ^= 1;
    }

    // epilogue
#pragma unroll
    for (int mt = 0; mt < 4; mt++) {
        const int r0 = bm + wm * 64 + mt * 16 + gr;
#pragma unroll
        for (int nt = 0; nt < 8; nt++) {
            const int cb = bn + wn * 64 + nt * 8 + 2 * cc;
            *(float2*)(C + (size_t)r0 * N + cb)       = make_float2(acc[mt][nt][0], acc[mt][nt][1]);
            *(float2*)(C + (size_t)(r0 + 8) * N + cb) = make_float2(acc[mt][nt][2], acc[mt][nt][3]);
        }
    }
}

// ---------------------------------------------------------------------------
// Flash attention, tf32 mma.sync (unchanged from R6: working, ~225us)
// ---------------------------------------------------------------------------
#define KSP 68
#define VSP 72
#define PSP 68
#define SM_KS (64 * KSP)
#define SM_VS (64 * VSP)
#define SM_PS (128 * PSP)
#define FLASH_SMEM ((SM_KS + SM_VS + SM_PS) * 4)

__global__ __launch_bounds__(256, 2)
void flash_tc(const float* __restrict__ Q, const float* __restrict__ K,
              const float* __restrict__ V, float* __restrict__ O,
              const int* __restrict__ maskflag)
{
    extern __shared__ float smf[];
    float* Ks = smf;                 // [n][d] pitch 68
    float* Vs = Ks + SM_KS;          // [n][d] pitch 72
    float* Ps = Vs + SM_VS;          // [m][n] pitch 68 (Q staging first)

    const int tid  = threadIdx.x;
    const int lane = tid & 31;
    const int warp = tid >> 5;
    const int gr   = lane >> 2;
    const int cc   = lane & 3;
    const int bh   = blockIdx.y;
    const int bx   = blockIdx.x;
    const int m0   = bx * 128;
    const int wr0  = warp * 16;

    const float* Qb = Q + (size_t)bh * PS * PHD;
    const float* Kb = K + (size_t)bh * PS * PHD;
    const float* Vb = V + (size_t)bh * PS * PHD;
    float*       Ob = O + (size_t)bh * PS * PHD + (size_t)m0 * PHD;

    for (int t = tid; t < 2048; t += 256) {
        int r = t >> 4, c4 = (t & 15) << 2;
        float4 x = *(const float4*)(Qb + (size_t)(m0 + r) * PHD + c4);
        float* d = &Ps[r * PSP + c4];
        d[0] = x.x * 0.125f; d[1] = x.y * 0.125f;
        d[2] = x.z * 0.125f; d[3] = x.w * 0.125f;
    }
    __syncthreads();

    uint32_t qa[8][4];
#pragma unroll
    for (int s = 0; s < 8; s++) {
        const int k8 = s * 8;
        qa[s][0] = f2tf32(Ps[(wr0 + gr) * PSP + k8 + cc]);
        qa[s][1] = f2tf32(Ps[(wr0 + gr + 8) * PSP + k8 + cc]);
        qa[s][2] = f2tf32(Ps[(wr0 + gr) * PSP + k8 + cc + 4]);
        qa[s][3] = f2tf32(Ps[(wr0 + gr + 8) * PSP + k8 + cc + 4]);
    }
    __syncwarp();

    const bool causal = (*maskflag != 0);
    const int ntiles = causal ? (2 * bx + 2) : (PS / 64);

    float mr0 = -1e30f, mr1 = -1e30f, lr0 = 0.f, lr1 = 0.f;
    float o[8][4];
#pragma unroll
    for (int nt = 0; nt < 8; nt++)
#pragma unroll
        for (int r = 0; r < 4; r++) o[nt][r] = 0.f;

    for (int kt = 0; kt < ntiles; kt++) {
        const int n0 = kt * 64;

        for (int t = tid; t < 1024; t += 256) {
            int r = t >> 4, c4 = (t & 15) << 2;
            float4 xk = *(const float4*)(Kb + (size_t)(n0 + r) * PHD + c4);
            float* kd = &Ks[r * KSP + c4];
            kd[0] = __uint_as_float(f2tf32(xk.x)); kd[1] = __uint_as_float(f2tf32(xk.y));
            kd[2] = __uint_as_float(f2tf32(xk.z)); kd[3] = __uint_as_float(f2tf32(xk.w));
            float4 xv = *(const float4*)(Vb + (size_t)(n0 + r) * PHD + c4);
            float* vd = &Vs[r * VSP + c4];
            vd[0] = __uint_as_float(f2tf32(xv.x)); vd[1] = __uint_as_float(f2tf32(xv.y));
            vd[2] = __uint_as_float(f2tf32(xv.z)); vd[3] = __uint_as_float(f2tf32(xv.w));
        }
        __syncthreads();

        float s[8][4];
#pragma unroll
        for (int nt = 0; nt < 8; nt++)
#pragma unroll
            for (int r = 0; r < 4; r++) s[nt][r] = 0.f;

#pragma unroll
        for (int ks = 0; ks < 8; ks++) {
            const int k8 = ks * 8;
#pragma unroll
            for (int nt = 0; nt < 8; nt++) {
                uint32_t b[2];
                b[0] = __float_as_uint(Ks[(nt * 8 + gr) * KSP + k8 + cc]);
                b[1] = __float_as_uint(Ks[(nt * 8 + gr) * KSP + k8 + cc + 4]);
                mma_tf32(s[nt], qa[ks], b);
            }
        }

        const int rlo = m0 + wr0 + gr;
        const int rhi = rlo + 8;
        if (causal && (n0 + 63 > rlo)) {
#pragma unroll
            for (int nt = 0; nt < 8; nt++) {
                const int c0 = n0 + nt * 8 + 2 * cc;
                if (c0 > rlo)     s[nt][0] = -1e30f;
                if (c0 + 1 > rlo) s[nt][1] = -1e30f;
                if (c0 > rhi)     s[nt][2] = -1e30f;
                if (c0 + 1 > rhi) s[nt][3] = -1e30f;
            }
        }

        float tl = -1e30f, th = -1e30f;
#pragma unroll
        for (int nt = 0; nt < 8; nt++) {
            tl = fmaxf(tl, fmaxf(s[nt][0], s[nt][1]));
            th = fmaxf(th, fmaxf(s[nt][2], s[nt][3]));
        }
        tl = fmaxf(tl, __shfl_xor_sync(0xffffffffu, tl, 1));
        tl = fmaxf(tl, __shfl_xor_sync(0xffffffffu, tl, 2));
        th = fmaxf(th, __shfl_xor_sync(0xffffffffu, th, 1));
        th = fmaxf(th, __shfl_xor_sync(0xffffffffu, th, 2));

        const float mn0 = fmaxf(mr0, tl);
        const float mn1 = fmaxf(mr1, th);
        const float al0 = __expf(mr0 - mn0);
        const float al1 = __expf(mr1 - mn1);

        float sl = 0.f, sh = 0.f;
#pragma unroll
        for (int nt = 0; nt < 8; nt++) {
            float p0 = __expf(s[nt][0] - mn0);
            float p1 = __expf(s[nt][1] - mn0);
            float p2 = __expf(s[nt][2] - mn1);
            float p3 = __expf(s[nt][3] - mn1);
            sl += p0 + p1; sh += p2 + p3;
            uint2 w0 = make_uint2(f2tf32(p0), f2tf32(p1));
            uint2 w1 = make_uint2(f2tf32(p2), f2tf32(p3));
            *(uint2*)&Ps[(wr0 + gr) * PSP + nt * 8 + 2 * cc]     = w0;
            *(uint2*)&Ps[(wr0 + gr + 8) * PSP + nt * 8 + 2 * cc] = w1;
        }
        sl += __shfl_xor_sync(0xffffffffu, sl, 1);
        sl += __shfl_xor_sync(0xffffffffu, sl, 2);
        sh += __shfl_xor_sync(0xffffffffu, sh, 1);
        sh += __shfl_xor_sync(0xffffffffu, sh, 2);

        lr0 = lr0 * al0 + sl;
        lr1 = lr1 * al1 + sh;
        mr0 = mn0; mr1 = mn1;

#pragma unroll
        for (int nt = 0; nt < 8; nt++) {
            o[nt][0] *= al0; o[nt][1] *= al0;
            o[nt][2] *= al1; o[nt][3] *= al1;
        }
        __syncwarp();

#pragma unroll
        for (int ks = 0; ks < 8; ks++) {
            const int k8 = ks * 8;
            uint32_t a[4];
            a[0] = __float_as_uint(Ps[(wr0 + gr) * PSP + k8 + cc]);
            a[1] = __float_as_uint(Ps[(wr0 + gr + 8) * PSP + k8 + cc]);
            a[2] = __float_as_uint(Ps[(wr0 + gr) * PSP + k8 + cc + 4]);
            a[3] = __float_as_uint(Ps[(wr0 + gr + 8) * PSP + k8 + cc + 4]);
#pragma unroll
            for (int nt = 0; nt < 8; nt++) {
                uint32_t b[2];
                b[0] = __float_as_uint(Vs[(k8 + cc) * VSP + nt * 8 + gr]);
                b[1] = __float_as_uint(Vs[(k8 + cc + 4) * VSP + nt * 8 + gr]);
                mma_tf32(o[nt], a, b);
            }
        }
        __syncthreads();
    }

    const float i0 = 1.0f / lr0;
    const float i1 = 1.0f / lr1;
#pragma unroll
    for (int nt = 0; nt < 8; nt++) {
        const int cb = nt * 8 + 2 * cc;
        *(float2*)(Ob + (size_t)(wr0 + gr) * PHD + cb) =
            make_float2(o[nt][0] * i0, o[nt][1] * i0);
        *(float2*)(Ob + (size_t)(wr0 + gr + 8) * PHD + cb) =
            make_float2(o[nt][2] * i1, o[nt][3] * i1);
    }
}

// ---------------------------------------------------------------------------
// Launch
// ---------------------------------------------------------------------------
extern "C" void kernel_launch(void* const* d_in, const int* in_sizes, int n_in,
                              void* d_out, int out_size)
{
    const float* q  = (const float*)d_in[0];
    const float* k  = (const float*)d_in[1];
    const float* v  = (const float*)d_in[2];
    const float* wq = (const float*)d_in[3];
    const float* wk = (const float*)d_in[4];
    const float* wv = (const float*)d_in[5];
    const float* wo = (const float*)d_in[6];
    const int*   am = (const int*)d_in[7];
    float* out = (float*)d_out;

    float *qp, *kp, *vp, *ao;
    cudaGetSymbolAddress((void**)&qp, g_qp);
    cudaGetSymbolAddress((void**)&kp, g_kp);
    cudaGetSymbolAddress((void**)&vp, g_vp);
    cudaGetSymbolAddress((void**)&ao, g_ao);

    cudaFuncSetAttribute(gemm_tc, cudaFuncAttributeMaxDynamicSharedMemorySize, GT_SMEM);
    cudaFuncSetAttribute(flash_tc, cudaFuncAttributeMaxDynamicSharedMemorySize, FLASH_SMEM);

    // fused Q/K/V projections (z = 0,1,2)
    dim3 gQKV(PE / 256, PM / 128, 3);   // (4, 32, 3)
    gemm_tc<<<gQKV, 256, GT_SMEM>>>(q, wq, qp,  k, wk, kp,  v, wv, vp, PM, PE, PE);

    dim3 gAttn(PS / 128, PBH);          // (16, 32)
    flash_tc<<<gAttn, 256, FLASH_SMEM>>>(qp, kp, vp, ao, am);

    // output projection
    dim3 gO(PE / 256, PM / 128, 1);
    gemm_tc<<<gO, 256, GT_SMEM>>>(ao, wo, out,  ao, wo, out,  ao, wo, out, PM, PE, PE);
}